// round 2
// baseline (speedup 1.0000x reference)
#include <cuda_runtime.h>
#include <math.h>

#define BB 8
#define TT 2048
#define SS 3
#define HH 12
#define WW 6
#define LL 512
#define NC 48          // channels in x: S*H + 3*N_NOISE = 36 + 12
#define NN 4
#define RR 4
#define NTAP 9

typedef unsigned long long ull;

__device__ __forceinline__ ull ffma2(ull a, ull b, ull c) {
    ull d;
    asm("fma.rn.f32x2 %0, %1, %2, %3;" : "=l"(d) : "l"(a), "l"(b), "l"(c));
    return d;
}

// ---------------- device globals (scratch; no allocation allowed) ----------
__device__ float g_envmean[BB][SS * HH];      // per-batch mean over T of env channels
__device__ float g_w[BB][NN][NTAP];           // normalized gaussian weights per (b, noise)

// ---------------- stats prepass --------------------------------------------
__global__ void stats_kernel(const float* __restrict__ x) {
    __shared__ float partial[8][NC];
    int b = blockIdx.x;
    int tid = threadIdx.x;            // 0..383
    int c = tid % NC;
    int r = tid / NC;
    float s = 0.f;
    const float* xb = x + (size_t)b * TT * NC;
    for (int t = r; t < TT; t += 8) s += xb[(size_t)t * NC + c];
    partial[r][c] = s;
    __syncthreads();
    if (tid < NC) {
        float tot = 0.f;
#pragma unroll
        for (int k = 0; k < 8; k++) tot += partial[k][tid];
        float mean = tot * (1.0f / TT);
        if (tid < SS * HH) {
            g_envmean[b][tid] = mean;
        } else {
            int rem = tid - SS * HH;
            if (rem % 3 == 2) {
                int i = rem / 3;
                float sigma = fmaxf(mean, 0.001f);
                float inv2s2 = 0.5f / (sigma * sigma);
                float ws[NTAP];
                float wsum = 0.f;
#pragma unroll
                for (int j = 0; j < NTAP; j++) {
                    float k = (float)(j - RR);
                    ws[j] = expf(-k * k * inv2s2);
                    wsum += ws[j];
                }
                float inv = 1.0f / wsum;
#pragma unroll
                for (int j = 0; j < NTAP; j++) g_w[b][i][j] = ws[j] * inv;
            }
        }
    }
}

// ---------------- main fused kernel ----------------------------------------
#define LCHUNK 128
#define TTILE 16
#define TILES_PER_BLOCK 16
#define LATS_BLOCKS 768           // 4 (l-chunks) * 8 (t-groups) * 24 (b*s)

// noise region flat-index thresholds (each item = 4 consecutive float4 = 16 floats)
// P=16:   8*2048*1  = 16384
// P=64:   8*2048*4  = 65536   -> cum 81920
// P=256:  8*2048*16 = 262144  -> cum 344064
// P=1024: 8*2048*64 = 1048576 -> cum 1392640
#define NQ_C0 16384
#define NQ_C1 81920
#define NQ_C2 344064
#define NQ_C3 1392640
#define NOISE_BLOCKS ((NQ_C3 + 191) / 192)   // 7254

__device__ __forceinline__ void lats_body(
    const float* __restrict__ x,
    const float* __restrict__ LT,
    float* __restrict__ out)
{
    __shared__ float  s_lat[HH * WW * LCHUNK];   // 36,864 B
    __shared__ float2 s_env2[TTILE][HH];         // env duplicated {e,e} for f32x2

    const int bl = blockIdx.x;
    const int lc = bl & 3;            // 0..3
    const int tg = (bl >> 2) & 7;     // 0..7
    const int bs = bl >> 5;           // 0..23
    const int b  = bs / SS;
    const int s  = bs % SS;
    const int tid = threadIdx.x;

    // Load 12x6x128 latents chunk for this segment into smem (float4)
    const int NV = HH * WW * (LCHUNK / 4);      // 2304
    for (int q = tid; q < NV; q += 192) {
        int hw = q / (LCHUNK / 4);
        int v  = q % (LCHUNK / 4);
        int h = hw / WW, w = hw % WW;
        size_t gidx = (((size_t)(s * HH + h)) * (SS * WW) + (s * WW + w)) * LL
                      + (size_t)lc * LCHUNK + v * 4;
        float4 val = *(const float4*)&LT[gidx];
        *(float4*)&s_lat[q * 4] = val;
    }

    const int w  = tid / 32;
    const int l4 = tid % 32;
    const float* em = &g_envmean[b][s * HH];
    const int ett = tid / HH;   // 0..15  (192 = 16*12 exactly)
    const int eh  = tid % HH;

    __syncthreads();

    for (int tile = 0; tile < TILES_PER_BLOCK; ++tile) {
        const int t0 = tg * (TILES_PER_BLOCK * TTILE) + tile * TTILE;

        // env tile: 16 t x 12 h, mean-subtracted, duplicated for packed math
        {
            float v = x[((size_t)(b * TT) + (t0 + ett)) * NC + s * HH + eh] - em[eh];
            s_env2[ett][eh] = make_float2(v, v);
        }
        __syncthreads();

        ull acc[TTILE][2];
#pragma unroll
        for (int ttr = 0; ttr < TTILE; ttr++) { acc[ttr][0] = 0ull; acc[ttr][1] = 0ull; }

#pragma unroll
        for (int h = 0; h < HH; h++) {
            union { float4 f; ull u[2]; } lv;
            lv.f = *(const float4*)&s_lat[(h * WW + w) * LCHUNK + l4 * 4];
#pragma unroll
            for (int ttr = 0; ttr < TTILE; ttr++) {
                ull e2 = *(const ull*)&s_env2[ttr][h];
                acc[ttr][0] = ffma2(e2, lv.u[0], acc[ttr][0]);
                acc[ttr][1] = ffma2(e2, lv.u[1], acc[ttr][1]);
            }
        }

#pragma unroll
        for (int ttr = 0; ttr < TTILE; ttr++) {
            size_t o = (((size_t)(b * TT + t0 + ttr)) * (SS * WW) + (s * WW + w)) * LL
                       + (size_t)lc * LCHUNK + l4 * 4;
            union { float4 f; ull u[2]; } r;
            r.u[0] = acc[ttr][0];
            r.u[1] = acc[ttr][1];
            __stcs((float4*)&out[o], r.f);
        }
        __syncthreads();
    }
}

// One noise item = 4 consecutive float4 (64B) of one (b,t) row.
template<int P, int NI>
__device__ __forceinline__ void noise_body(
    int q,
    const float* __restrict__ x,
    const float* __restrict__ eps,
    float* __restrict__ out)   // region base
{
    constexpr int G = P / 16;             // items per (b,t) row
    const int g = q % G;
    const int t = (q / G) % TT;
    const int b = q / (G * TT);

    float wloc[NTAP];
    {
        const float* wr = g_w[b][NI];
#pragma unroll
        for (int j = 0; j < NTAP; j++) wloc[j] = wr[j];
    }
    const float* xb = x + (size_t)b * TT * NC + SS * HH + 3 * NI;
    const float* eb = eps + (size_t)b * TT * P + g * 16;

    float4 acc[4];
#pragma unroll
    for (int k = 0; k < 4; k++) acc[k] = make_float4(0.f, 0.f, 0.f, 0.f);

#pragma unroll
    for (int j = 0; j < NTAP; j++) {
        int idx = t + j - RR;
        idx = (idx < 0) ? -idx : idx;
        idx = (idx >= TT) ? (2 * TT - 2 - idx) : idx;
        float wj = wloc[j];
        float mu = xb[(size_t)idx * NC];
        float sg = xb[(size_t)idx * NC + 1];
        const float4* ep = (const float4*)(eb + (size_t)idx * P);
#pragma unroll
        for (int k = 0; k < 4; k++) {
            float4 e = ep[k];
            acc[k].x = fmaf(wj, fmaf(sg, e.x, mu), acc[k].x);
            acc[k].y = fmaf(wj, fmaf(sg, e.y, mu), acc[k].y);
            acc[k].z = fmaf(wj, fmaf(sg, e.z, mu), acc[k].z);
            acc[k].w = fmaf(wj, fmaf(sg, e.w, mu), acc[k].w);
        }
    }

    float* ob = out + ((size_t)b * TT + t) * P + g * 16;
#pragma unroll
    for (int k = 0; k < 4; k++) __stcs((float4*)&ob[k * 4], acc[k]);
}

__global__ __launch_bounds__(192) void main_kernel(
    const float* __restrict__ x,
    const float* __restrict__ LT,
    const float* __restrict__ e0,
    const float* __restrict__ e1,
    const float* __restrict__ e2,
    const float* __restrict__ e3,
    float* __restrict__ out)
{
    const size_t LATS = (size_t)BB * TT * (SS * WW) * LL;
    const size_t N0   = (size_t)BB * TT * 16;
    const size_t N1   = (size_t)BB * TT * 64;
    const size_t N2   = (size_t)BB * TT * 256;

    if (blockIdx.x < LATS_BLOCKS) {
        lats_body(x, LT, out);
    } else {
        int q = (blockIdx.x - LATS_BLOCKS) * 192 + threadIdx.x;
        if (q < NQ_C0) {
            noise_body<16, 0>(q, x, e0, out + LATS);
        } else if (q < NQ_C1) {
            noise_body<64, 1>(q - NQ_C0, x, e1, out + LATS + N0);
        } else if (q < NQ_C2) {
            noise_body<256, 2>(q - NQ_C1, x, e2, out + LATS + N0 + N1);
        } else if (q < NQ_C3) {
            noise_body<1024, 3>(q - NQ_C2, x, e3, out + LATS + N0 + N1 + N2);
        }
    }
}

// ---------------- launch ----------------------------------------------------
extern "C" void kernel_launch(void* const* d_in, const int* in_sizes, int n_in,
                              void* d_out, int out_size) {
    const float* x  = (const float*)d_in[0];
    const float* LT = (const float*)d_in[1];
    const float* e0 = (const float*)d_in[2];
    const float* e1 = (const float*)d_in[3];
    const float* e2 = (const float*)d_in[4];
    const float* e3 = (const float*)d_in[5];
    float* out = (float*)d_out;

    stats_kernel<<<BB, 384>>>(x);
    main_kernel<<<LATS_BLOCKS + NOISE_BLOCKS, 192>>>(x, LT, e0, e1, e2, e3, out);
}

// round 3
// speedup vs baseline: 1.3760x; 1.3760x over previous
#include <cuda_runtime.h>
#include <math.h>

#define BB 8
#define TT 2048
#define SS 3
#define HH 12
#define WW 6
#define LL 512
#define NC 48          // channels in x: S*H + 3*N_NOISE = 36 + 12
#define NN 4
#define RR 4
#define NTAP 9

typedef unsigned long long ull;

__device__ __forceinline__ ull ffma2(ull a, ull b, ull c) {
    ull d;
    asm("fma.rn.f32x2 %0, %1, %2, %3;" : "=l"(d) : "l"(a), "l"(b), "l"(c));
    return d;
}

// ---------------- device globals ----------
__device__ float g_envmean[BB][SS * HH];
__device__ float g_w[BB][NN][NTAP];

// ---------------- stats prepass --------------------------------------------
__global__ void stats_kernel(const float* __restrict__ x) {
    __shared__ float partial[8][NC];
    int b = blockIdx.x;
    int tid = threadIdx.x;            // 0..383
    int c = tid % NC;
    int r = tid / NC;
    float s = 0.f;
    const float* xb = x + (size_t)b * TT * NC;
    for (int t = r; t < TT; t += 8) s += xb[(size_t)t * NC + c];
    partial[r][c] = s;
    __syncthreads();
    if (tid < NC) {
        float tot = 0.f;
#pragma unroll
        for (int k = 0; k < 8; k++) tot += partial[k][tid];
        float mean = tot * (1.0f / TT);
        if (tid < SS * HH) {
            g_envmean[b][tid] = mean;
        } else {
            int rem = tid - SS * HH;
            if (rem % 3 == 2) {
                int i = rem / 3;
                float sigma = fmaxf(mean, 0.001f);
                float inv2s2 = 0.5f / (sigma * sigma);
                float ws[NTAP];
                float wsum = 0.f;
#pragma unroll
                for (int j = 0; j < NTAP; j++) {
                    float k = (float)(j - RR);
                    ws[j] = expf(-k * k * inv2s2);
                    wsum += ws[j];
                }
                float inv = 1.0f / wsum;
#pragma unroll
                for (int j = 0; j < NTAP; j++) g_w[b][i][j] = ws[j] * inv;
            }
        }
    }
}

// ---------------- fused main kernel ----------------------------------------
#define LCHUNK 128
#define TTILE 8            // t-rows per register tile
#define TCHUNK 32          // t-rows staged in smem env per refill
#define TSPAN 512          // t-rows per block
#define LATS_BLOCKS 384    // 4 lc * 4 tg * 24 bs

// noise: one item = 4 consecutive float4 (16 floats) of one (b,t) row
#define NQ_C0 16384        // P=16
#define NQ_C1 81920        // + P=64
#define NQ_C2 344064       // + P=256
#define NQ_C3 1392640      // + P=1024
#define NOISE_BLOCKS ((NQ_C3 + 191) / 192)   // 7254

__device__ __forceinline__ void lats_body(
    const float* __restrict__ x,
    const float* __restrict__ LT,
    float* __restrict__ out)
{
    __shared__ float  s_lat[HH * WW * LCHUNK];     // 36,864 B
    __shared__ float2 s_env2[HH][TCHUNK];          // 3,072 B, pairs {e,e}, t-adjacent

    const int bl = blockIdx.x;
    const int lc = bl & 3;            // 0..3
    const int tg = (bl >> 2) & 3;     // 0..3
    const int bs = bl >> 4;           // 0..23
    const int b  = bs / SS;
    const int s  = bs % SS;
    const int tid = threadIdx.x;

    // Load 12x6x128 latents chunk into smem (float4)
    const int NV = HH * WW * (LCHUNK / 4);      // 2304
    for (int q = tid; q < NV; q += 192) {
        int hw = q / (LCHUNK / 4);
        int v  = q % (LCHUNK / 4);
        int h = hw / WW, w = hw % WW;
        size_t gidx = (((size_t)(s * HH + h)) * (SS * WW) + (s * WW + w)) * LL
                      + (size_t)lc * LCHUNK + v * 4;
        float4 val = *(const float4*)&LT[gidx];
        *(float4*)&s_lat[q * 4] = val;
    }

    const int w  = tid / 32;
    const int l4 = tid % 32;
    const float* em = &g_envmean[b][s * HH];
    const float* latp = &s_lat[w * LCHUNK + l4 * 4];   // step HH stride WW*LCHUNK

    // env fill indices: 384 entries (h*TCHUNK + tt); each thread fills 2
    const int e0h = tid / TCHUNK, e0t = tid % TCHUNK;
    const int e1h = (tid + 192) / TCHUNK, e1t = (tid + 192) % TCHUNK;

    __syncthreads();

    const int tbase0 = tg * TSPAN;
    for (int tc = 0; tc < TSPAN / TCHUNK; ++tc) {
        const int tb = tbase0 + tc * TCHUNK;
        // stage env chunk, mean-subtracted, duplicated
        {
            float v0 = x[((size_t)(b * TT) + (tb + e0t)) * NC + s * HH + e0h] - em[e0h];
            s_env2[e0h][e0t] = make_float2(v0, v0);
            float v1 = x[((size_t)(b * TT) + (tb + e1t)) * NC + s * HH + e1h] - em[e1h];
            s_env2[e1h][e1t] = make_float2(v1, v1);
        }
        __syncthreads();

#pragma unroll
        for (int sub = 0; sub < TCHUNK / TTILE; ++sub) {
            ull acc[TTILE][2];
#pragma unroll
            for (int t = 0; t < TTILE; t++) { acc[t][0] = 0ull; acc[t][1] = 0ull; }

#pragma unroll
            for (int h = 0; h < HH; h++) {
                union { float4 f; ull u[2]; } lv;
                lv.f = *(const float4*)&latp[h * (WW * LCHUNK)];
#pragma unroll
                for (int k = 0; k < TTILE / 2; k++) {
                    // one LDS.128 broadcast = env pairs for t = 2k, 2k+1
                    union { float4 f; ull u[2]; } ep;
                    ep.f = *(const float4*)&s_env2[h][sub * TTILE + 2 * k];
                    acc[2*k][0]   = ffma2(ep.u[0], lv.u[0], acc[2*k][0]);
                    acc[2*k][1]   = ffma2(ep.u[0], lv.u[1], acc[2*k][1]);
                    acc[2*k+1][0] = ffma2(ep.u[1], lv.u[0], acc[2*k+1][0]);
                    acc[2*k+1][1] = ffma2(ep.u[1], lv.u[1], acc[2*k+1][1]);
                }
            }

            const int t0 = tb + sub * TTILE;
#pragma unroll
            for (int t = 0; t < TTILE; t++) {
                size_t o = (((size_t)(b * TT + t0 + t)) * (SS * WW) + (s * WW + w)) * LL
                           + (size_t)lc * LCHUNK + l4 * 4;
                union { float4 f; ull u[2]; } r;
                r.u[0] = acc[t][0];
                r.u[1] = acc[t][1];
                __stcs((float4*)&out[o], r.f);
            }
        }
        __syncthreads();   // protect s_env2 before refill
    }
}

// One noise item = 4 consecutive float4 (64B) of one (b,t) row.
template<int P, int NI>
__device__ __forceinline__ void noise_body(
    int q,
    const float* __restrict__ x,
    const float* __restrict__ eps,
    float* __restrict__ out)
{
    constexpr int G = P / 16;
    const int g = q % G;
    const int t = (q / G) % TT;
    const int b = q / (G * TT);

    float wloc[NTAP];
    {
        const float* wr = g_w[b][NI];
#pragma unroll
        for (int j = 0; j < NTAP; j++) wloc[j] = wr[j];
    }
    const float* xb = x + (size_t)b * TT * NC + SS * HH + 3 * NI;
    const float* eb = eps + (size_t)b * TT * P + g * 16;

    float4 acc[4];
#pragma unroll
    for (int k = 0; k < 4; k++) acc[k] = make_float4(0.f, 0.f, 0.f, 0.f);

#pragma unroll
    for (int j = 0; j < NTAP; j++) {
        int idx = t + j - RR;
        idx = (idx < 0) ? -idx : idx;
        idx = (idx >= TT) ? (2 * TT - 2 - idx) : idx;
        float wj = wloc[j];
        float mu = xb[(size_t)idx * NC];
        float sg = xb[(size_t)idx * NC + 1];
        const float4* ep = (const float4*)(eb + (size_t)idx * P);
#pragma unroll
        for (int k = 0; k < 4; k++) {
            float4 e = ep[k];
            acc[k].x = fmaf(wj, fmaf(sg, e.x, mu), acc[k].x);
            acc[k].y = fmaf(wj, fmaf(sg, e.y, mu), acc[k].y);
            acc[k].z = fmaf(wj, fmaf(sg, e.z, mu), acc[k].z);
            acc[k].w = fmaf(wj, fmaf(sg, e.w, mu), acc[k].w);
        }
    }

    float* ob = out + ((size_t)b * TT + t) * P + g * 16;
#pragma unroll
    for (int k = 0; k < 4; k++) __stcs((float4*)&ob[k * 4], acc[k]);
}

__global__ __launch_bounds__(192, 3) void main_kernel(
    const float* __restrict__ x,
    const float* __restrict__ LT,
    const float* __restrict__ e0,
    const float* __restrict__ e1,
    const float* __restrict__ e2,
    const float* __restrict__ e3,
    float* __restrict__ out)
{
    const size_t LATS = (size_t)BB * TT * (SS * WW) * LL;
    const size_t N0   = (size_t)BB * TT * 16;
    const size_t N1   = (size_t)BB * TT * 64;
    const size_t N2   = (size_t)BB * TT * 256;

    if (blockIdx.x < LATS_BLOCKS) {
        lats_body(x, LT, out);
    } else {
        int q = (blockIdx.x - LATS_BLOCKS) * 192 + threadIdx.x;
        if (q < NQ_C0) {
            noise_body<16, 0>(q, x, e0, out + LATS);
        } else if (q < NQ_C1) {
            noise_body<64, 1>(q - NQ_C0, x, e1, out + LATS + N0);
        } else if (q < NQ_C2) {
            noise_body<256, 2>(q - NQ_C1, x, e2, out + LATS + N0 + N1);
        } else if (q < NQ_C3) {
            noise_body<1024, 3>(q - NQ_C2, x, e3, out + LATS + N0 + N1 + N2);
        }
    }
}

// ---------------- launch ----------------------------------------------------
extern "C" void kernel_launch(void* const* d_in, const int* in_sizes, int n_in,
                              void* d_out, int out_size) {
    const float* x  = (const float*)d_in[0];
    const float* LT = (const float*)d_in[1];
    const float* e0 = (const float*)d_in[2];
    const float* e1 = (const float*)d_in[3];
    const float* e2 = (const float*)d_in[4];
    const float* e3 = (const float*)d_in[5];
    float* out = (float*)d_out;

    stats_kernel<<<BB, 384>>>(x);
    main_kernel<<<LATS_BLOCKS + NOISE_BLOCKS, 192>>>(x, LT, e0, e1, e2, e3, out);
}

// round 4
// speedup vs baseline: 1.9008x; 1.3814x over previous
#include <cuda_runtime.h>
#include <math.h>

#define BB 8
#define TT 2048
#define SS 3
#define HH 12
#define WW 6
#define LL 512
#define NC 48
#define NN 4
#define RR 4
#define NTAP 9

typedef unsigned long long ull;

__device__ __forceinline__ ull ffma2(ull a, ull b, ull c) {
    ull d;
    asm("fma.rn.f32x2 %0, %1, %2, %3;" : "=l"(d) : "l"(a), "l"(b), "l"(c));
    return d;
}

// ---------------- device globals ----------
__device__ float g_envmean[BB][SS * HH];
__device__ float g_w[BB][NN][NTAP];

// ---------------- stats prepass --------------------------------------------
__global__ void stats_kernel(const float* __restrict__ x) {
    __shared__ float partial[8][NC];
    int b = blockIdx.x;
    int tid = threadIdx.x;            // 0..383
    int c = tid % NC;
    int r = tid / NC;
    float s = 0.f;
    const float* xb = x + (size_t)b * TT * NC;
    for (int t = r; t < TT; t += 8) s += xb[(size_t)t * NC + c];
    partial[r][c] = s;
    __syncthreads();
    if (tid < NC) {
        float tot = 0.f;
#pragma unroll
        for (int k = 0; k < 8; k++) tot += partial[k][tid];
        float mean = tot * (1.0f / TT);
        if (tid < SS * HH) {
            g_envmean[b][tid] = mean;
        } else {
            int rem = tid - SS * HH;
            if (rem % 3 == 2) {
                int i = rem / 3;
                float sigma = fmaxf(mean, 0.001f);
                float inv2s2 = 0.5f / (sigma * sigma);
                float ws[NTAP];
                float wsum = 0.f;
#pragma unroll
                for (int j = 0; j < NTAP; j++) {
                    float k = (float)(j - RR);
                    ws[j] = expf(-k * k * inv2s2);
                    wsum += ws[j];
                }
                float inv = 1.0f / wsum;
#pragma unroll
                for (int j = 0; j < NTAP; j++) g_w[b][i][j] = ws[j] * inv;
            }
        }
    }
}

// ---------------- fused main kernel ----------------------------------------
#define LCHUNK 128
#define TTILE 8
#define TCHUNK 32
#define TSPAN 512
#define LATS_BLOCKS 384    // 4 lc * 4 tg * 24 bs

// noise: one item = one float4 column x 8 consecutive t
// G4 = P/4 columns; items = B * (T/8) * G4
// P=16:   8*256*4   = 8192
// P=64:   8*256*16  = 32768  -> cum 40960
// P=256:  8*256*64  = 131072 -> cum 172032
// P=1024: 8*256*256 = 524288 -> cum 696320
#define NQ_C0 8192
#define NQ_C1 40960
#define NQ_C2 172032
#define NQ_C3 696320
#define NOISE_BLOCKS ((NQ_C3 + 191) / 192)   // 3627

__device__ __forceinline__ void lats_body(
    const float* __restrict__ x,
    const float* __restrict__ LT,
    float* __restrict__ out)
{
    __shared__ float2 s_env2[HH][TCHUNK];          // 3,072 B, pairs {e,e}

    const int bl = blockIdx.x;
    const int lc = bl & 3;            // 0..3
    const int tg = (bl >> 2) & 3;     // 0..3
    const int bs = bl >> 4;           // 0..23
    const int b  = bs / SS;
    const int s  = bs % SS;
    const int tid = threadIdx.x;
    const int w  = tid / 32;
    const int l4 = tid % 32;

    // Load this thread's 12 lat float4 values into registers (once per block)
    ull lat[HH][2];
#pragma unroll
    for (int h = 0; h < HH; h++) {
        size_t gidx = (((size_t)(s * HH + h)) * (SS * WW) + (s * WW + w)) * LL
                      + (size_t)lc * LCHUNK + l4 * 4;
        union { float4 f; ull u[2]; } lv;
        lv.f = __ldg((const float4*)&LT[gidx]);
        lat[h][0] = lv.u[0];
        lat[h][1] = lv.u[1];
    }

    const float* em = &g_envmean[b][s * HH];
    // env fill indices: 384 entries (h*TCHUNK + tt); each thread fills 2
    const int e0h = tid / TCHUNK, e0t = tid % TCHUNK;
    const int e1h = (tid + 192) / TCHUNK, e1t = (tid + 192) % TCHUNK;
    const float em0 = em[e0h];
    const float em1 = em[e1h];

    const int tbase0 = tg * TSPAN;
    for (int tc = 0; tc < TSPAN / TCHUNK; ++tc) {
        const int tb = tbase0 + tc * TCHUNK;
        {
            float v0 = x[((size_t)(b * TT) + (tb + e0t)) * NC + s * HH + e0h] - em0;
            s_env2[e0h][e0t] = make_float2(v0, v0);
            float v1 = x[((size_t)(b * TT) + (tb + e1t)) * NC + s * HH + e1h] - em1;
            s_env2[e1h][e1t] = make_float2(v1, v1);
        }
        __syncthreads();

#pragma unroll
        for (int sub = 0; sub < TCHUNK / TTILE; ++sub) {
            ull acc[TTILE][2];
#pragma unroll
            for (int t = 0; t < TTILE; t++) { acc[t][0] = 0ull; acc[t][1] = 0ull; }

#pragma unroll
            for (int h = 0; h < HH; h++) {
#pragma unroll
                for (int k = 0; k < TTILE / 2; k++) {
                    union { float4 f; ull u[2]; } ep;
                    ep.f = *(const float4*)&s_env2[h][sub * TTILE + 2 * k];
                    acc[2*k][0]   = ffma2(ep.u[0], lat[h][0], acc[2*k][0]);
                    acc[2*k][1]   = ffma2(ep.u[0], lat[h][1], acc[2*k][1]);
                    acc[2*k+1][0] = ffma2(ep.u[1], lat[h][0], acc[2*k+1][0]);
                    acc[2*k+1][1] = ffma2(ep.u[1], lat[h][1], acc[2*k+1][1]);
                }
            }

            const int t0 = tb + sub * TTILE;
#pragma unroll
            for (int t = 0; t < TTILE; t++) {
                size_t o = (((size_t)(b * TT + t0 + t)) * (SS * WW) + (s * WW + w)) * LL
                           + (size_t)lc * LCHUNK + l4 * 4;
                union { float4 f; ull u[2]; } r;
                r.u[0] = acc[t][0];
                r.u[1] = acc[t][1];
                __stcs((float4*)&out[o], r.f);
            }
        }
        __syncthreads();
    }
}

__device__ __forceinline__ int refl(int i) {
    i = (i < 0) ? -i : i;
    return (i >= TT) ? (2 * TT - 2 - i) : i;
}

// One noise item = one float4 column for 8 consecutive t (sliding window).
template<int P, int NI>
__device__ __forceinline__ void noise_body(
    int q,
    const float* __restrict__ x,
    const float* __restrict__ eps,
    float* __restrict__ out)
{
    constexpr int G4 = P / 4;
    const int g  = q % G4;
    const int tg = (q / G4) % (TT / 8);
    const int b  = q / (G4 * (TT / 8));
    const int t0 = tg * 8;

    float wl[NTAP];
    {
        const float* wr = g_w[b][NI];
#pragma unroll
        for (int j = 0; j < NTAP; j++) wl[j] = wr[j];
    }
    const float* xb = x + (size_t)b * TT * NC + SS * HH + 3 * NI;
    const float* eb = eps + (size_t)b * TT * P + g * 4;
    float* ob = out + ((size_t)b * TT + t0) * P + g * 4;

    float4 win[NTAP];
#pragma unroll
    for (int j = 0; j < NTAP; j++) {
        int idx = refl(t0 - RR + j);
        float mu = xb[(size_t)idx * NC];
        float sg = xb[(size_t)idx * NC + 1];
        float4 e = *(const float4*)&eb[(size_t)idx * P];
        win[j] = make_float4(fmaf(sg, e.x, mu), fmaf(sg, e.y, mu),
                             fmaf(sg, e.z, mu), fmaf(sg, e.w, mu));
    }

#pragma unroll
    for (int k = 0; k < 8; k++) {
        float4 a = make_float4(0.f, 0.f, 0.f, 0.f);
#pragma unroll
        for (int j = 0; j < NTAP; j++) {
            float4 v = win[(j + k) % NTAP];
            float wj = wl[j];
            a.x = fmaf(wj, v.x, a.x);
            a.y = fmaf(wj, v.y, a.y);
            a.z = fmaf(wj, v.z, a.z);
            a.w = fmaf(wj, v.w, a.w);
        }
        __stcs((float4*)&ob[(size_t)k * P], a);
        // refill oldest slot with v(t0 + k + 5)
        int idx = refl(t0 + k + RR + 1);
        float mu = xb[(size_t)idx * NC];
        float sg = xb[(size_t)idx * NC + 1];
        float4 e = *(const float4*)&eb[(size_t)idx * P];
        win[k % NTAP] = make_float4(fmaf(sg, e.x, mu), fmaf(sg, e.y, mu),
                                    fmaf(sg, e.z, mu), fmaf(sg, e.w, mu));
    }
}

__global__ __launch_bounds__(192, 3) void main_kernel(
    const float* __restrict__ x,
    const float* __restrict__ LT,
    const float* __restrict__ e0,
    const float* __restrict__ e1,
    const float* __restrict__ e2,
    const float* __restrict__ e3,
    float* __restrict__ out)
{
    const size_t LATS = (size_t)BB * TT * (SS * WW) * LL;
    const size_t N0   = (size_t)BB * TT * 16;
    const size_t N1   = (size_t)BB * TT * 64;
    const size_t N2   = (size_t)BB * TT * 256;

    if (blockIdx.x < LATS_BLOCKS) {
        lats_body(x, LT, out);
    } else {
        int q = (blockIdx.x - LATS_BLOCKS) * 192 + threadIdx.x;
        if (q < NQ_C0) {
            noise_body<16, 0>(q, x, e0, out + LATS);
        } else if (q < NQ_C1) {
            noise_body<64, 1>(q - NQ_C0, x, e1, out + LATS + N0);
        } else if (q < NQ_C2) {
            noise_body<256, 2>(q - NQ_C1, x, e2, out + LATS + N0 + N1);
        } else if (q < NQ_C3) {
            noise_body<1024, 3>(q - NQ_C2, x, e3, out + LATS + N0 + N1 + N2);
        }
    }
}

// ---------------- launch ----------------------------------------------------
extern "C" void kernel_launch(void* const* d_in, const int* in_sizes, int n_in,
                              void* d_out, int out_size) {
    const float* x  = (const float*)d_in[0];
    const float* LT = (const float*)d_in[1];
    const float* e0 = (const float*)d_in[2];
    const float* e1 = (const float*)d_in[3];
    const float* e2 = (const float*)d_in[4];
    const float* e3 = (const float*)d_in[5];
    float* out = (float*)d_out;

    stats_kernel<<<BB, 384>>>(x);
    main_kernel<<<LATS_BLOCKS + NOISE_BLOCKS, 192>>>(x, LT, e0, e1, e2, e3, out);
}